// round 14
// baseline (speedup 1.0000x reference)
#include <cuda_runtime.h>

// ---------------------------------------------------------------------------
// B=16, N=7, Lq=256, Lp=512, D=768, S=12, Wq=200, Wp=400
// word slots: q 3200, p 6400, n 44800 -> 54400
// out floats: q_pooled[0,12288) p_pooled[12288,24576)
//             q_logits[24576,62976) p_logits[62976,139776) n_pooled[139776,225792)
// ---------------------------------------------------------------------------
#define TOTAL_WORDS 54400
#define OFF_QPOOL 0
#define OFF_PPOOL 12288
#define OFF_QLOG  24576
#define OFF_PLOG  62976
#define OFF_NPOOL 139776

// g_acc[w*16 + 0..11] = logit sums, [w*16+12] = count (pitch 16 -> kB reads
// 3 aligned LDG.128 + 1 scalar; 13..15 unused)
__device__ float g_acc[TOTAL_WORDS * 16];
__device__ float g_coef[TOTAL_WORDS];
__device__ unsigned g_ticket;

typedef unsigned long long u64;

__device__ __forceinline__ u64 pack2(float x) {
    u64 r; asm("mov.b64 %0, {%1, %1};" : "=l"(r) : "f"(x)); return r;
}
__device__ __forceinline__ u64 pack2(float lo, float hi) {
    u64 r; asm("mov.b64 %0, {%1, %2};" : "=l"(r) : "f"(lo), "f"(hi)); return r;
}
__device__ __forceinline__ void fma2(u64& a, u64 x, u64 y) {
    asm("fma.rn.f32x2 %0, %1, %2, %0;" : "+l"(a) : "l"(x), "l"(y));
}
__device__ __forceinline__ u64 add2(u64 x, u64 y) {
    u64 r; asm("add.rn.f32x2 %0, %1, %2;" : "=l"(r) : "l"(x), "l"(y)); return r;
}
__device__ __forceinline__ float2 unpack2(u64 v) {
    float2 r; asm("mov.b64 {%0, %1}, %2;" : "=f"(r.x), "=f"(r.y) : "l"(v)); return r;
}

// ---------------------------------------------------------------------------
// Kernel A: per-token projection h[768]@W[768x12] + segment atomics.
//   sub = lane&7 covers d = sub*4 + 32*i + k (i 0..23, k 0..3)
//   grp = lane>>3, tokens = grp + 4*tt, tt 0..3 -> 16 tokens/pass
// 3 rotating register buffers; loads issued 2-3 compute blocks ahead.
// KEY CHANGE vs champion: __launch_bounds__(128, 3) -> 168-reg budget so the
// ~150 live registers of the pipeline (3x16-float4 bufs + 24-u64 acc) fit
// WITHOUT ptxas collapsing the prefetch distance (previous (128,4) clamped
// at exactly 128 regs -> distance silently shortened -> 54% DRAM plateau).
// Occupancy 12 warps/SM; per-warp demand 4 LDG.128/block keeps DRAM fed.
// Weights: smem chunks [c][k*6+j], pitch 26 u64 (39936B); conflict-free
// LDS.128 (sub byte offsets mod 128 = {0,80,32,112,64,16,96,48}).
// Work: 4352 passes of 16 tokens, per-warp global ticket for balance.
// ---------------------------------------------------------------------------
#define WSLOT 26
#define NPASS_TOTAL 4352
#define KA_BLOCKS 444   // 148 SM * 3 CTAs

#define KA_LD(I, V0, V1, V2, V3)                                               \
    {                                                                          \
        V0 = __ldcs((const float4*)(hbg +        (I) * 32));                   \
        V1 = __ldcs((const float4*)(hbg + 3072 + (I) * 32));                   \
        V2 = __ldcs((const float4*)(hbg + 6144 + (I) * 32));                   \
        V3 = __ldcs((const float4*)(hbg + 9216 + (I) * 32));                   \
    }

#define KA_COMPUTE(I, A0, A1, A2, A3)                                          \
    {                                                                          \
        const u64* wr = swl + (I) * (8 * WSLOT);                               \
        _Pragma("unroll")                                                      \
        for (int k = 0; k < 4; k++) {                                          \
            u64 h0 = pack2(((const float*)&A0)[k]);                            \
            u64 h1 = pack2(((const float*)&A1)[k]);                            \
            u64 hv2 = pack2(((const float*)&A2)[k]);                           \
            u64 h3 = pack2(((const float*)&A3)[k]);                            \
            ulonglong2 w01 = *(const ulonglong2*)(wr + k * 6);                 \
            ulonglong2 w23 = *(const ulonglong2*)(wr + k * 6 + 2);             \
            ulonglong2 w45 = *(const ulonglong2*)(wr + k * 6 + 4);             \
            fma2(acc[0][0], h0, w01.x); fma2(acc[0][1], h0, w01.y);            \
            fma2(acc[0][2], h0, w23.x); fma2(acc[0][3], h0, w23.y);            \
            fma2(acc[0][4], h0, w45.x); fma2(acc[0][5], h0, w45.y);            \
            fma2(acc[1][0], h1, w01.x); fma2(acc[1][1], h1, w01.y);            \
            fma2(acc[1][2], h1, w23.x); fma2(acc[1][3], h1, w23.y);            \
            fma2(acc[1][4], h1, w45.x); fma2(acc[1][5], h1, w45.y);            \
            fma2(acc[2][0], hv2, w01.x); fma2(acc[2][1], hv2, w01.y);          \
            fma2(acc[2][2], hv2, w23.x); fma2(acc[2][3], hv2, w23.y);          \
            fma2(acc[2][4], hv2, w45.x); fma2(acc[2][5], hv2, w45.y);          \
            fma2(acc[3][0], h3, w01.x); fma2(acc[3][1], h3, w01.y);            \
            fma2(acc[3][2], h3, w23.x); fma2(acc[3][3], h3, w23.y);            \
            fma2(acc[3][4], h3, w45.x); fma2(acc[3][5], h3, w45.y);            \
        }                                                                      \
    }

__global__ __launch_bounds__(128, 3) void kA(
    const float* __restrict__ qh, const float* __restrict__ ph, const float* __restrict__ nh,
    const int* __restrict__ qw, const int* __restrict__ pw, const int* __restrict__ nwid,
    const float* __restrict__ projw)
{
    __shared__ __align__(16) u64 sw[192 * WSLOT];   // 39936 bytes
    for (int idx = threadIdx.x; idx < 768 * 6; idx += 128) {
        int d = idx / 6, j = idx % 6;
        sw[(d >> 2) * WSLOT + (d & 3) * 6 + j] =
            pack2(projw[d * 12 + 2 * j], projw[d * 12 + 2 * j + 1]);
    }
    __syncthreads();

    const int lane = threadIdx.x & 31;
    const int sub  = lane & 7;
    const int grp  = lane >> 3;
    const u64* swl = sw + sub * WSLOT;

    for (;;) {
        unsigned t;
        if (lane == 0) t = atomicAdd(&g_ticket, 1u);
        t = __shfl_sync(0xffffffffu, t, 0);
        if (t >= NPASS_TOTAL) break;
        const int p = (int)t;

        const float* hid; const int* wid; int logL, W, wb, lp;
        if (p < 256)      { hid = qh; wid = qw;   logL = 8; W = 200; wb = 0;    lp = p; }
        else if (p < 768) { hid = ph; wid = pw;   logL = 9; W = 400; wb = 3200; lp = p - 256; }
        else              { hid = nh; wid = nwid; logL = 9; W = 400; wb = 9600; lp = p - 768; }

        const int tokBase = lp << 4;                 // 16 tokens
        const int m = tokBase >> logL;
        const float* hbg = hid + (size_t)tokBase * 768 + (size_t)grp * 768 + sub * 4;

        u64 acc[4][6];
        #pragma unroll
        for (int tt = 0; tt < 4; tt++)
            #pragma unroll
            for (int j = 0; j < 6; j++) acc[tt][j] = 0ull;

        float4 A0, A1, A2, A3, B0, B1, B2, B3, C0, C1, C2, C3;
        KA_LD(0, A0, A1, A2, A3);
        KA_LD(1, B0, B1, B2, B3);

        #pragma unroll 1
        for (int i = 0; i < 21; i += 3) {
            KA_LD(i + 2, C0, C1, C2, C3);
            KA_COMPUTE(i, A0, A1, A2, A3);
            KA_LD(i + 3, A0, A1, A2, A3);
            KA_COMPUTE(i + 1, B0, B1, B2, B3);
            KA_LD(i + 4, B0, B1, B2, B3);
            KA_COMPUTE(i + 2, C0, C1, C2, C3);
        }
        KA_LD(23, C0, C1, C2, C3);
        KA_COMPUTE(21, A0, A1, A2, A3);
        KA_COMPUTE(22, B0, B1, B2, B3);
        KA_COMPUTE(23, C0, C1, C2, C3);

        // reduce across the 8 sub-lanes (xor 1,2,4 stay inside the octet)
        #pragma unroll
        for (int tt = 0; tt < 4; tt++)
            #pragma unroll
            for (int j = 0; j < 6; j++) {
                u64 v = acc[tt][j];
                v = add2(v, __shfl_xor_sync(0xffffffffu, v, 1));
                v = add2(v, __shfl_xor_sync(0xffffffffu, v, 2));
                v = add2(v, __shfl_xor_sync(0xffffffffu, v, 4));
                acc[tt][j] = v;
            }

        if (sub == 0) {
            #pragma unroll
            for (int tt = 0; tt < 4; tt++) {
                int tok = tokBase + grp + 4 * tt;
                float* ls = g_acc + (size_t)(wb + m * W + wid[tok]) * 16;
                #pragma unroll
                for (int j = 0; j < 6; j++) {
                    float2 f = unpack2(acc[tt][j]);
                    atomicAdd(ls + 2 * j,     f.x);
                    atomicAdd(ls + 2 * j + 1, f.y);
                }
                atomicAdd(ls + 12, 1.0f);
            }
        }
    }
}

// ---------------------------------------------------------------------------
// Kernel B: per sample — scope softmax -> importance, masked word softmax ->
// per-word coefficient weight/count; writes q/p logits. 144 blocks x 128.
// pitch-16 g_acc: per-word read = 3x LDG.128 + 1 LDG.32, all parallel.
// ---------------------------------------------------------------------------
__global__ __launch_bounds__(128) void kB(const float* __restrict__ projb,
                                          const float* __restrict__ simp,
                                          float* __restrict__ out)
{
    const int blk = blockIdx.x;
    int W, wb; float* lout = nullptr;
    if (blk < 16)      { W = 200; wb = blk * 200;                    lout = out + OFF_QLOG + blk * 200 * 12; }
    else if (blk < 32) { int m = blk - 16; W = 400; wb = 3200 + m * 400; lout = out + OFF_PLOG + m * 400 * 12; }
    else               { int m = blk - 32; W = 400; wb = 9600 + m * 400; }

    __shared__ float impbuf[400];
    __shared__ float red[4];
    const int tid = threadIdx.x;

    float b[12], si[12];
    #pragma unroll
    for (int s = 0; s < 12; s++) { b[s] = projb[s]; si[s] = simp[s]; }

    for (int w = tid; w < W; w += 128) {
        const float4* ls4 = (const float4*)(g_acc + (size_t)(wb + w) * 16);
        float4 v0 = ls4[0];
        float4 v1 = ls4[1];
        float4 v2 = ls4[2];
        float  c  = ((const float*)ls4)[12];
        float imp;
        if (c > 0.f) {
            float l[12], mx = -1e30f;
            float invc = 1.f / c;
            l[0] = v0.x * invc + b[0];  l[1] = v0.y * invc + b[1];
            l[2] = v0.z * invc + b[2];  l[3] = v0.w * invc + b[3];
            l[4] = v1.x * invc + b[4];  l[5] = v1.y * invc + b[5];
            l[6] = v1.z * invc + b[6];  l[7] = v1.w * invc + b[7];
            l[8] = v2.x * invc + b[8];  l[9] = v2.y * invc + b[9];
            l[10] = v2.z * invc + b[10]; l[11] = v2.w * invc + b[11];
            #pragma unroll
            for (int s = 0; s < 12; s++) mx = fmaxf(mx, l[s]);
            float se = 0.f, ai = 0.f;
            #pragma unroll
            for (int s = 0; s < 12; s++) {
                float e = __expf(l[s] - mx);
                se += e; ai += e * si[s];
            }
            imp = ai / se;
            if (lout) {
                #pragma unroll
                for (int s = 0; s < 12; s++) lout[w * 12 + s] = l[s];
            }
        } else {
            imp = -1e4f;
            if (lout) {
                #pragma unroll
                for (int s = 0; s < 12; s++) lout[w * 12 + s] = 0.f;
            }
        }
        impbuf[w] = imp;
    }
    __syncthreads();

    float mx = -1e30f;
    for (int w = tid; w < W; w += 128) mx = fmaxf(mx, impbuf[w]);
    #pragma unroll
    for (int o = 16; o; o >>= 1) mx = fmaxf(mx, __shfl_xor_sync(0xffffffffu, mx, o));
    if ((tid & 31) == 0) red[tid >> 5] = mx;
    __syncthreads();
    mx = fmaxf(fmaxf(red[0], red[1]), fmaxf(red[2], red[3]));
    __syncthreads();

    float se = 0.f;
    for (int w = tid; w < W; w += 128) se += __expf(impbuf[w] - mx);
    #pragma unroll
    for (int o = 16; o; o >>= 1) se += __shfl_xor_sync(0xffffffffu, se, o);
    if ((tid & 31) == 0) red[tid >> 5] = se;
    __syncthreads();
    se = red[0] + red[1] + red[2] + red[3];
    const float inv = 1.f / se;

    for (int w = tid; w < W; w += 128) {
        float c = g_acc[(size_t)(wb + w) * 16 + 12];
        g_coef[wb + w] = (c > 0.f) ? (__expf(impbuf[w] - mx) * inv) / c : 0.f;
    }
}

// ---------------------------------------------------------------------------
// Kernel C: pooled[m,:] += sum over 64-token slab coef[m, wid] * h[m,tok,:]
// 1088 blocks x 192 threads, float4/thread, __ldcs streaming (measured at
// ~7.9 TB/s effective — BW ceiling; do not touch).
// ---------------------------------------------------------------------------
__global__ __launch_bounds__(192) void kC(
    const float* __restrict__ qh, const float* __restrict__ ph, const float* __restrict__ nh,
    const int* __restrict__ qw, const int* __restrict__ pw, const int* __restrict__ nwid,
    float* __restrict__ out)
{
    const int blk = blockIdx.x;
    const float* hid; const int* wid; int L, wb, m, slab; float* po;
    if (blk < 64)       { m = blk >> 2;  slab = blk & 3; hid = qh; wid = qw;   L = 256; wb = m * 200;        po = out + OFF_QPOOL + m * 768; }
    else if (blk < 192) { int b2 = blk - 64;  m = b2 >> 3; slab = b2 & 7; hid = ph; wid = pw;   L = 512; wb = 3200 + m * 400; po = out + OFF_PPOOL + m * 768; }
    else                { int b2 = blk - 192; m = b2 >> 3; slab = b2 & 7; hid = nh; wid = nwid; L = 512; wb = 9600 + m * 400; po = out + OFF_NPOOL + m * 768; }

    __shared__ float cf[64];
    const int tid = threadIdx.x;
    const int t0 = slab * 64;
    if (tid < 64) cf[tid] = g_coef[wb + wid[m * L + t0 + tid]];
    __syncthreads();

    const float* hp = hid + (size_t)(m * L + t0) * 768 + tid * 4;
    float ax = 0.f, ay = 0.f, az = 0.f, aw = 0.f;
    #pragma unroll 8
    for (int t = 0; t < 64; t++) {
        float c = cf[t];
        float4 v = __ldcs((const float4*)(hp + (size_t)t * 768));
        ax += c * v.x; ay += c * v.y; az += c * v.z; aw += c * v.w;
    }
    float* o = po + tid * 4;
    atomicAdd(o + 0, ax);
    atomicAdd(o + 1, ay);
    atomicAdd(o + 2, az);
    atomicAdd(o + 3, aw);
}

// ---------------------------------------------------------------------------
extern "C" void kernel_launch(void* const* d_in, const int* in_sizes, int n_in,
                              void* d_out, int out_size)
{
    const float* qh    = (const float*)d_in[0];
    const float* ph    = (const float*)d_in[1];
    const float* nh    = (const float*)d_in[2];
    const float* projw = (const float*)d_in[3];
    const float* projb = (const float*)d_in[4];
    const float* simp  = (const float*)d_in[5];
    const int*   qw    = (const int*)d_in[6];
    const int*   pw    = (const int*)d_in[7];
    const int*   nwid  = (const int*)d_in[8];
    float* out = (float*)d_out;

    void* pacc = nullptr; cudaGetSymbolAddress(&pacc, g_acc);
    void* ptck = nullptr; cudaGetSymbolAddress(&ptck, g_ticket);
    cudaMemsetAsync(pacc, 0, sizeof(float) * TOTAL_WORDS * 16);
    cudaMemsetAsync(ptck, 0, sizeof(unsigned));
    cudaMemsetAsync(out + OFF_QPOOL, 0, sizeof(float) * 24576);   // q_pooled + p_pooled
    cudaMemsetAsync(out + OFF_NPOOL, 0, sizeof(float) * 86016);   // n_pooled

    kA<<<KA_BLOCKS, 128>>>(qh, ph, nh, qw, pw, nwid, projw);
    kB<<<144, 128>>>(projb, simp, out);
    kC<<<1088, 192>>>(qh, ph, nh, qw, pw, nwid, out);
}

// round 15
// speedup vs baseline: 1.1406x; 1.1406x over previous
#include <cuda_runtime.h>

// ---------------------------------------------------------------------------
// B=16, N=7, Lq=256, Lp=512, D=768, S=12, Wq=200, Wp=400
// word slots: q 3200, p 6400, n 44800 -> 54400
// out floats: q_pooled[0,12288) p_pooled[12288,24576)
//             q_logits[24576,62976) p_logits[62976,139776) n_pooled[139776,225792)
// ---------------------------------------------------------------------------
#define TOTAL_WORDS 54400
#define OFF_QPOOL 0
#define OFF_PPOOL 12288
#define OFF_QLOG  24576
#define OFF_PLOG  62976
#define OFF_NPOOL 139776

// g_acc[w*16 + 0..11] = logit sums, [w*16+12] = count (pitch 16 -> kB reads
// 3 aligned LDG.128 + 1 scalar; 13..15 unused)
__device__ float g_acc[TOTAL_WORDS * 16];
__device__ float g_coef[TOTAL_WORDS];

typedef unsigned long long u64;

__device__ __forceinline__ u64 pack2(float x) {
    u64 r; asm("mov.b64 %0, {%1, %1};" : "=l"(r) : "f"(x)); return r;
}
__device__ __forceinline__ u64 pack2(float lo, float hi) {
    u64 r; asm("mov.b64 %0, {%1, %2};" : "=l"(r) : "f"(lo), "f"(hi)); return r;
}
__device__ __forceinline__ void fma2(u64& a, u64 x, u64 y) {
    asm("fma.rn.f32x2 %0, %1, %2, %0;" : "+l"(a) : "l"(x), "l"(y));
}
__device__ __forceinline__ u64 add2(u64 x, u64 y) {
    u64 r; asm("add.rn.f32x2 %0, %1, %2;" : "=l"(r) : "l"(x), "l"(y)); return r;
}
__device__ __forceinline__ float2 unpack2(u64 v) {
    float2 r; asm("mov.b64 {%0, %1}, %2;" : "=f"(r.x), "=f"(r.y) : "l"(v)); return r;
}

// ---------------------------------------------------------------------------
// Kernel A (champion R6 config): per-token projection h[768]@W[768x12] +
// segment atomics.
//   sub = lane&7 covers d = sub*4 + 32*i + k (i 0..23, k 0..3)
//   grp = lane>>3, tokens = grp + 4*tt, tt 0..3 -> 16 tokens/pass
// 3 rotating register buffers; loads issued 2-3 compute blocks ahead; __ldcs.
// Weights: smem chunks [c][k*6+j], pitch 26 u64 (39936B); conflict-free
// LDS.128 (sub byte offsets mod 128 = {0,80,32,112,64,16,96,48}).
// Passes: 69632/16 = 4352; grid 544*4 warps = 2176 -> exactly 2 passes/warp.
// Ledger (R7/R9/R14): this geometry is the measured optimum of the
// fma-issue / weight-LDS-crossbar / LDG-return contention triangle; both
// more warps (R7) and more regs (R14) regress.
// ---------------------------------------------------------------------------
#define WSLOT 26
#define NPASS_TOTAL 4352
#define KA_BLOCKS 544

#define KA_LD(I, V0, V1, V2, V3)                                               \
    {                                                                          \
        V0 = __ldcs((const float4*)(hbg +        (I) * 32));                   \
        V1 = __ldcs((const float4*)(hbg + 3072 + (I) * 32));                   \
        V2 = __ldcs((const float4*)(hbg + 6144 + (I) * 32));                   \
        V3 = __ldcs((const float4*)(hbg + 9216 + (I) * 32));                   \
    }

#define KA_COMPUTE(I, A0, A1, A2, A3)                                          \
    {                                                                          \
        const u64* wr = swl + (I) * (8 * WSLOT);                               \
        _Pragma("unroll")                                                      \
        for (int k = 0; k < 4; k++) {                                          \
            u64 h0 = pack2(((const float*)&A0)[k]);                            \
            u64 h1 = pack2(((const float*)&A1)[k]);                            \
            u64 hv2 = pack2(((const float*)&A2)[k]);                           \
            u64 h3 = pack2(((const float*)&A3)[k]);                            \
            ulonglong2 w01 = *(const ulonglong2*)(wr + k * 6);                 \
            ulonglong2 w23 = *(const ulonglong2*)(wr + k * 6 + 2);             \
            ulonglong2 w45 = *(const ulonglong2*)(wr + k * 6 + 4);             \
            fma2(acc[0][0], h0, w01.x); fma2(acc[0][1], h0, w01.y);            \
            fma2(acc[0][2], h0, w23.x); fma2(acc[0][3], h0, w23.y);            \
            fma2(acc[0][4], h0, w45.x); fma2(acc[0][5], h0, w45.y);            \
            fma2(acc[1][0], h1, w01.x); fma2(acc[1][1], h1, w01.y);            \
            fma2(acc[1][2], h1, w23.x); fma2(acc[1][3], h1, w23.y);            \
            fma2(acc[1][4], h1, w45.x); fma2(acc[1][5], h1, w45.y);            \
            fma2(acc[2][0], hv2, w01.x); fma2(acc[2][1], hv2, w01.y);          \
            fma2(acc[2][2], hv2, w23.x); fma2(acc[2][3], hv2, w23.y);          \
            fma2(acc[2][4], hv2, w45.x); fma2(acc[2][5], hv2, w45.y);          \
            fma2(acc[3][0], h3, w01.x); fma2(acc[3][1], h3, w01.y);            \
            fma2(acc[3][2], h3, w23.x); fma2(acc[3][3], h3, w23.y);            \
            fma2(acc[3][4], h3, w45.x); fma2(acc[3][5], h3, w45.y);            \
        }                                                                      \
    }

__global__ __launch_bounds__(128, 4) void kA(
    const float* __restrict__ qh, const float* __restrict__ ph, const float* __restrict__ nh,
    const int* __restrict__ qw, const int* __restrict__ pw, const int* __restrict__ nwid,
    const float* __restrict__ projw)
{
    __shared__ __align__(16) u64 sw[192 * WSLOT];   // 39936 bytes
    for (int idx = threadIdx.x; idx < 768 * 6; idx += 128) {
        int d = idx / 6, j = idx % 6;
        sw[(d >> 2) * WSLOT + (d & 3) * 6 + j] =
            pack2(projw[d * 12 + 2 * j], projw[d * 12 + 2 * j + 1]);
    }
    __syncthreads();

    const int lane = threadIdx.x & 31;
    const int sub  = lane & 7;
    const int grp  = lane >> 3;
    const int gw   = (blockIdx.x * blockDim.x + threadIdx.x) >> 5;
    const int nwarps = (KA_BLOCKS * 128) >> 5;
    const u64* swl = sw + sub * WSLOT;

    for (int p = gw; p < NPASS_TOTAL; p += nwarps) {
        const float* hid; const int* wid; int logL, W, wb, lp;
        if (p < 256)      { hid = qh; wid = qw;   logL = 8; W = 200; wb = 0;    lp = p; }
        else if (p < 768) { hid = ph; wid = pw;   logL = 9; W = 400; wb = 3200; lp = p - 256; }
        else              { hid = nh; wid = nwid; logL = 9; W = 400; wb = 9600; lp = p - 768; }

        const int tokBase = lp << 4;                 // 16 tokens
        const int m = tokBase >> logL;
        const float* hbg = hid + (size_t)tokBase * 768 + (size_t)grp * 768 + sub * 4;

        u64 acc[4][6];
        #pragma unroll
        for (int tt = 0; tt < 4; tt++)
            #pragma unroll
            for (int j = 0; j < 6; j++) acc[tt][j] = 0ull;

        float4 A0, A1, A2, A3, B0, B1, B2, B3, C0, C1, C2, C3;
        KA_LD(0, A0, A1, A2, A3);
        KA_LD(1, B0, B1, B2, B3);

        #pragma unroll 1
        for (int i = 0; i < 21; i += 3) {
            KA_LD(i + 2, C0, C1, C2, C3);
            KA_COMPUTE(i, A0, A1, A2, A3);
            KA_LD(i + 3, A0, A1, A2, A3);
            KA_COMPUTE(i + 1, B0, B1, B2, B3);
            KA_LD(i + 4, B0, B1, B2, B3);
            KA_COMPUTE(i + 2, C0, C1, C2, C3);
        }
        KA_LD(23, C0, C1, C2, C3);
        KA_COMPUTE(21, A0, A1, A2, A3);
        KA_COMPUTE(22, B0, B1, B2, B3);
        KA_COMPUTE(23, C0, C1, C2, C3);

        // reduce across the 8 sub-lanes (xor 1,2,4 stay inside the octet)
        #pragma unroll
        for (int tt = 0; tt < 4; tt++)
            #pragma unroll
            for (int j = 0; j < 6; j++) {
                u64 v = acc[tt][j];
                v = add2(v, __shfl_xor_sync(0xffffffffu, v, 1));
                v = add2(v, __shfl_xor_sync(0xffffffffu, v, 2));
                v = add2(v, __shfl_xor_sync(0xffffffffu, v, 4));
                acc[tt][j] = v;
            }

        if (sub == 0) {
            #pragma unroll
            for (int tt = 0; tt < 4; tt++) {
                int tok = tokBase + grp + 4 * tt;
                float* ls = g_acc + (size_t)(wb + m * W + wid[tok]) * 16;
                #pragma unroll
                for (int j = 0; j < 6; j++) {
                    float2 f = unpack2(acc[tt][j]);
                    atomicAdd(ls + 2 * j,     f.x);
                    atomicAdd(ls + 2 * j + 1, f.y);
                }
                atomicAdd(ls + 12, 1.0f);
            }
        }
    }
}

// ---------------------------------------------------------------------------
// Kernel B: per sample — scope softmax -> importance, masked word softmax ->
// per-word coefficient weight/count; writes q/p logits. 144 blocks x 128.
// ALSO zeroes this sample's pooled output vector (replaces the two output
// memset launches; kB->kC kernel ordering guarantees the zero lands before
// kC's atomic accumulation).
// ---------------------------------------------------------------------------
__global__ __launch_bounds__(128) void kB(const float* __restrict__ projb,
                                          const float* __restrict__ simp,
                                          float* __restrict__ out)
{
    const int blk = blockIdx.x;
    int W, wb; float* lout = nullptr; float* pzero;
    if (blk < 16)      { W = 200; wb = blk * 200;                    lout = out + OFF_QLOG + blk * 200 * 12;
                         pzero = out + OFF_QPOOL + blk * 768; }
    else if (blk < 32) { int m = blk - 16; W = 400; wb = 3200 + m * 400; lout = out + OFF_PLOG + m * 400 * 12;
                         pzero = out + OFF_PPOOL + m * 768; }
    else               { int m = blk - 32; W = 400; wb = 9600 + m * 400;
                         pzero = out + OFF_NPOOL + m * 768; }

    __shared__ float impbuf[400];
    __shared__ float red[4];
    const int tid = threadIdx.x;

    // zero this sample's pooled vector: 192 float4 = 768 floats
    {
        float4 z = make_float4(0.f, 0.f, 0.f, 0.f);
        ((float4*)pzero)[tid] = z;
        if (tid < 64) ((float4*)pzero)[128 + tid] = z;
    }

    float b[12], si[12];
    #pragma unroll
    for (int s = 0; s < 12; s++) { b[s] = projb[s]; si[s] = simp[s]; }

    for (int w = tid; w < W; w += 128) {
        const float4* ls4 = (const float4*)(g_acc + (size_t)(wb + w) * 16);
        float4 v0 = ls4[0];
        float4 v1 = ls4[1];
        float4 v2 = ls4[2];
        float  c  = ((const float*)ls4)[12];
        float imp;
        if (c > 0.f) {
            float l[12], mx = -1e30f;
            float invc = 1.f / c;
            l[0] = v0.x * invc + b[0];  l[1] = v0.y * invc + b[1];
            l[2] = v0.z * invc + b[2];  l[3] = v0.w * invc + b[3];
            l[4] = v1.x * invc + b[4];  l[5] = v1.y * invc + b[5];
            l[6] = v1.z * invc + b[6];  l[7] = v1.w * invc + b[7];
            l[8] = v2.x * invc + b[8];  l[9] = v2.y * invc + b[9];
            l[10] = v2.z * invc + b[10]; l[11] = v2.w * invc + b[11];
            #pragma unroll
            for (int s = 0; s < 12; s++) mx = fmaxf(mx, l[s]);
            float se = 0.f, ai = 0.f;
            #pragma unroll
            for (int s = 0; s < 12; s++) {
                float e = __expf(l[s] - mx);
                se += e; ai += e * si[s];
            }
            imp = ai / se;
            if (lout) {
                #pragma unroll
                for (int s = 0; s < 12; s++) lout[w * 12 + s] = l[s];
            }
        } else {
            imp = -1e4f;
            if (lout) {
                #pragma unroll
                for (int s = 0; s < 12; s++) lout[w * 12 + s] = 0.f;
            }
        }
        impbuf[w] = imp;
    }
    __syncthreads();

    float mx = -1e30f;
    for (int w = tid; w < W; w += 128) mx = fmaxf(mx, impbuf[w]);
    #pragma unroll
    for (int o = 16; o; o >>= 1) mx = fmaxf(mx, __shfl_xor_sync(0xffffffffu, mx, o));
    if ((tid & 31) == 0) red[tid >> 5] = mx;
    __syncthreads();
    mx = fmaxf(fmaxf(red[0], red[1]), fmaxf(red[2], red[3]));
    __syncthreads();

    float se = 0.f;
    for (int w = tid; w < W; w += 128) se += __expf(impbuf[w] - mx);
    #pragma unroll
    for (int o = 16; o; o >>= 1) se += __shfl_xor_sync(0xffffffffu, se, o);
    if ((tid & 31) == 0) red[tid >> 5] = se;
    __syncthreads();
    se = red[0] + red[1] + red[2] + red[3];
    const float inv = 1.f / se;

    for (int w = tid; w < W; w += 128) {
        float c = g_acc[(size_t)(wb + w) * 16 + 12];
        g_coef[wb + w] = (c > 0.f) ? (__expf(impbuf[w] - mx) * inv) / c : 0.f;
    }
}

// ---------------------------------------------------------------------------
// Kernel C: pooled[m,:] += sum over 64-token slab coef[m, wid] * h[m,tok,:]
// 1088 blocks x 192 threads, float4/thread, __ldcs streaming (measured at
// the HBM ceiling — do not touch).
// ---------------------------------------------------------------------------
__global__ __launch_bounds__(192) void kC(
    const float* __restrict__ qh, const float* __restrict__ ph, const float* __restrict__ nh,
    const int* __restrict__ qw, const int* __restrict__ pw, const int* __restrict__ nwid,
    float* __restrict__ out)
{
    const int blk = blockIdx.x;
    const float* hid; const int* wid; int L, wb, m, slab; float* po;
    if (blk < 64)       { m = blk >> 2;  slab = blk & 3; hid = qh; wid = qw;   L = 256; wb = m * 200;        po = out + OFF_QPOOL + m * 768; }
    else if (blk < 192) { int b2 = blk - 64;  m = b2 >> 3; slab = b2 & 7; hid = ph; wid = pw;   L = 512; wb = 3200 + m * 400; po = out + OFF_PPOOL + m * 768; }
    else                { int b2 = blk - 192; m = b2 >> 3; slab = b2 & 7; hid = nh; wid = nwid; L = 512; wb = 9600 + m * 400; po = out + OFF_NPOOL + m * 768; }

    __shared__ float cf[64];
    const int tid = threadIdx.x;
    const int t0 = slab * 64;
    if (tid < 64) cf[tid] = g_coef[wb + wid[m * L + t0 + tid]];
    __syncthreads();

    const float* hp = hid + (size_t)(m * L + t0) * 768 + tid * 4;
    float ax = 0.f, ay = 0.f, az = 0.f, aw = 0.f;
    #pragma unroll 8
    for (int t = 0; t < 64; t++) {
        float c = cf[t];
        float4 v = __ldcs((const float4*)(hp + (size_t)t * 768));
        ax += c * v.x; ay += c * v.y; az += c * v.z; aw += c * v.w;
    }
    float* o = po + tid * 4;
    atomicAdd(o + 0, ax);
    atomicAdd(o + 1, ay);
    atomicAdd(o + 2, az);
    atomicAdd(o + 3, aw);
}

// ---------------------------------------------------------------------------
extern "C" void kernel_launch(void* const* d_in, const int* in_sizes, int n_in,
                              void* d_out, int out_size)
{
    const float* qh    = (const float*)d_in[0];
    const float* ph    = (const float*)d_in[1];
    const float* nh    = (const float*)d_in[2];
    const float* projw = (const float*)d_in[3];
    const float* projb = (const float*)d_in[4];
    const float* simp  = (const float*)d_in[5];
    const int*   qw    = (const int*)d_in[6];
    const int*   pw    = (const int*)d_in[7];
    const int*   nwid  = (const int*)d_in[8];
    float* out = (float*)d_out;

    void* pacc = nullptr; cudaGetSymbolAddress(&pacc, g_acc);
    cudaMemsetAsync(pacc, 0, sizeof(float) * TOTAL_WORDS * 16);

    kA<<<KA_BLOCKS, 128>>>(qh, ph, nh, qw, pw, nwid, projw);
    kB<<<144, 128>>>(projb, simp, out);
    kC<<<1088, 192>>>(qh, ph, nh, qw, pw, nwid, out);
}